// round 1
// baseline (speedup 1.0000x reference)
#include <cuda_runtime.h>

#define NPTS 1048576
#define HD 32
#define NB 4
#define TPB 128

typedef unsigned long long u64;

// ---- packed f32x2 helpers (Blackwell) ----
__device__ __forceinline__ u64 pk2(float a, float b) {
    u64 r; asm("mov.b64 %0, {%1, %2};" : "=l"(r) : "f"(a), "f"(b)); return r;
}
__device__ __forceinline__ void unpk2(u64 v, float& a, float& b) {
    asm("mov.b64 {%0, %1}, %2;" : "=f"(a), "=f"(b) : "l"(v));
}
__device__ __forceinline__ u64 splat2(float w) { return pk2(w, w); }
__device__ __forceinline__ u64 ffma2(u64 a, u64 b, u64 c) {
    u64 d; asm("fma.rn.f32x2 %0, %1, %2, %3;" : "=l"(d) : "l"(a), "l"(b), "l"(c));
    return d;
}

// tanh(x) = 1 - 2/(e^{2x}+1).  EX2 + RCP on MUFU; exact at both saturations
// (e->inf => 1, e->0 => -1).  Accuracy ~1e-7 rel, far inside the 1e-3 gate.
__device__ __forceinline__ float ftanh(float x) {
    float e = __expf(2.0f * x);
    return 1.0f - __fdividef(2.0f, e + 1.0f);
}
__device__ __forceinline__ u64 tanh2(u64 v) {
    float a, b; unpk2(v, a, b);
    return pk2(ftanh(a), ftanh(b));
}

__global__ __launch_bounds__(TPB)
void pfnn_kernel(const float* __restrict__ x,
                 const float* __restrict__ W0, const float* __restrict__ b0,
                 const float* __restrict__ W1, const float* __restrict__ b1,
                 const float* __restrict__ W2, const float* __restrict__ b2,
                 const float* __restrict__ W3, const float* __restrict__ b3,
                 float* __restrict__ out) {
    // Weights in shared.  W1/W2 stored TRANSPOSED as [b][j][d] so the inner
    // reduction over d reads contiguous float4 rows (LDS.128 broadcast).
    __shared__ float sW0[NB][3][HD];
    __shared__ float sB0[NB][HD];
    __shared__ __align__(16) float sW1[NB][HD][HD];
    __shared__ float sB1[NB][HD];
    __shared__ __align__(16) float sW2[NB][HD][HD];
    __shared__ float sB2[NB][HD];
    __shared__ __align__(16) float sW3[NB][HD];
    __shared__ float sB3[NB];

    for (int i = threadIdx.x; i < NB * 3 * HD; i += TPB) ((float*)sW0)[i] = W0[i];
    for (int i = threadIdx.x; i < NB * HD; i += TPB) {
        ((float*)sB0)[i] = b0[i];
        ((float*)sB1)[i] = b1[i];
        ((float*)sB2)[i] = b2[i];
        ((float*)sW3)[i] = W3[i];   // [B,H,1] -> flat [B][H]
    }
    for (int i = threadIdx.x; i < NB * HD * HD; i += TPB) {
        int b = i >> 10, r = i & 1023, d = r >> 5, j = r & 31;
        sW1[b][j][d] = W1[i];       // transpose on the fly
        sW2[b][j][d] = W2[i];
    }
    if (threadIdx.x < NB) sB3[threadIdx.x] = b3[threadIdx.x];
    __syncthreads();

    int t = blockIdx.x * TPB + threadIdx.x;
    int n0 = t * 2;
    if (n0 >= NPTS) return;

    // two consecutive points packed lane-wise into f32x2
    const float* xp = x + (long)n0 * 3;
    u64 px0 = pk2(xp[0], xp[3]);
    u64 px1 = pk2(xp[1], xp[4]);
    u64 px2 = pk2(xp[2], xp[5]);

    float outA[NB], outB[NB];

    #pragma unroll 1
    for (int b = 0; b < NB; b++) {
        u64 h[HD], g[HD];

        // ---- layer 0: 3 -> 32 ----
        #pragma unroll
        for (int j = 0; j < HD; j++) {
            u64 acc = splat2(sB0[b][j]);
            acc = ffma2(px0, splat2(sW0[b][0][j]), acc);
            acc = ffma2(px1, splat2(sW0[b][1][j]), acc);
            acc = ffma2(px2, splat2(sW0[b][2][j]), acc);
            h[j] = tanh2(acc);
        }

        // ---- layer 1: 32 -> 32 ----
        #pragma unroll
        for (int j = 0; j < HD; j++) {
            const float4* wr = (const float4*)&sW1[b][j][0];
            u64 acc = splat2(sB1[b][j]);
            #pragma unroll
            for (int q = 0; q < HD / 4; q++) {
                float4 w = wr[q];
                acc = ffma2(h[4*q+0], splat2(w.x), acc);
                acc = ffma2(h[4*q+1], splat2(w.y), acc);
                acc = ffma2(h[4*q+2], splat2(w.z), acc);
                acc = ffma2(h[4*q+3], splat2(w.w), acc);
            }
            g[j] = tanh2(acc);
        }

        // ---- layer 2: 32 -> 32 ----
        #pragma unroll
        for (int j = 0; j < HD; j++) {
            const float4* wr = (const float4*)&sW2[b][j][0];
            u64 acc = splat2(sB2[b][j]);
            #pragma unroll
            for (int q = 0; q < HD / 4; q++) {
                float4 w = wr[q];
                acc = ffma2(g[4*q+0], splat2(w.x), acc);
                acc = ffma2(g[4*q+1], splat2(w.y), acc);
                acc = ffma2(g[4*q+2], splat2(w.z), acc);
                acc = ffma2(g[4*q+3], splat2(w.w), acc);
            }
            h[j] = tanh2(acc);
        }

        // ---- layer 3: 32 -> 1 ----
        {
            const float4* wr = (const float4*)&sW3[b][0];
            u64 acc = splat2(sB3[b]);
            #pragma unroll
            for (int q = 0; q < HD / 4; q++) {
                float4 w = wr[q];
                acc = ffma2(h[4*q+0], splat2(w.x), acc);
                acc = ffma2(h[4*q+1], splat2(w.y), acc);
                acc = ffma2(h[4*q+2], splat2(w.z), acc);
                acc = ffma2(h[4*q+3], splat2(w.w), acc);
            }
            float oa, ob; unpk2(acc, oa, ob);
            outA[b] = oa; outB[b] = ob;
        }
    }

    // out is [N, 4] row-major: one float4 row per point
    float4* op = (float4*)out;
    op[n0]     = make_float4(outA[0], outA[1], outA[2], outA[3]);
    op[n0 + 1] = make_float4(outB[0], outB[1], outB[2], outB[3]);
}

extern "C" void kernel_launch(void* const* d_in, const int* in_sizes, int n_in,
                              void* d_out, int out_size) {
    const float* x  = (const float*)d_in[0];
    const float* W0 = (const float*)d_in[1];
    const float* b0 = (const float*)d_in[2];
    const float* W1 = (const float*)d_in[3];
    const float* b1 = (const float*)d_in[4];
    const float* W2 = (const float*)d_in[5];
    const float* b2 = (const float*)d_in[6];
    const float* W3 = (const float*)d_in[7];
    const float* b3 = (const float*)d_in[8];
    float* out = (float*)d_out;

    int pairs = NPTS / 2;
    int grid = (pairs + TPB - 1) / TPB;   // 4096
    pfnn_kernel<<<grid, TPB>>>(x, W0, b0, W1, b1, W2, b2, W3, b3, out);
}

// round 2
// speedup vs baseline: 1.2478x; 1.2478x over previous
#include <cuda_runtime.h>
#include <cstdint>

#define NPTS 1048576
#define HD 32
#define NB 4
#define TPB 256

typedef unsigned long long u64;

// ---- packed f32x2 helpers (Blackwell) ----
__device__ __forceinline__ u64 splat2(float w) {
    u64 r; asm("mov.b64 %0, {%1, %1};" : "=l"(r) : "f"(w)); return r;
}
__device__ __forceinline__ u64 ffma2(u64 a, u64 b, u64 c) {
    u64 d; asm("fma.rn.f32x2 %0, %1, %2, %3;" : "=l"(d) : "l"(a), "l"(b), "l"(c));
    return d;
}
__device__ __forceinline__ void unpk2(u64 v, float& a, float& b) {
    asm("mov.b64 {%0, %1}, %2;" : "=f"(a), "=f"(b) : "l"(v));
}
// LDS.128 returning two 64-bit lanes == two pre-packed f32x2 weight pairs
__device__ __forceinline__ void lds128(u64& a, u64& b, uint32_t addr) {
    asm volatile("ld.shared.v2.u64 {%0, %1}, [%2];" : "=l"(a), "=l"(b) : "r"(addr));
}
__device__ __forceinline__ u64 lds64(uint32_t addr) {
    u64 a; asm volatile("ld.shared.u64 %0, [%1];" : "=l"(a) : "r"(addr));
    return a;
}
__device__ __forceinline__ float tanh_fast(float x) {
    float y; asm("tanh.approx.f32 %0, %1;" : "=f"(y) : "f"(x));
    return y;
}

__global__ __launch_bounds__(TPB, 2)
void pfnn_kernel(const float* __restrict__ x,
                 const float* __restrict__ W0, const float* __restrict__ b0,
                 const float* __restrict__ W1, const float* __restrict__ b1,
                 const float* __restrict__ W2, const float* __restrict__ b2,
                 const float* __restrict__ W3, const float* __restrict__ b3,
                 float* __restrict__ out) {
    // Weights kept in ORIGINAL [b][d][j] layout (j contiguous): LDS.128 over j
    // yields two f32x2 weight pairs directly in register pairs. No transpose,
    // no splat on the weight path.
    __shared__ __align__(16) float sW0[NB * 3 * HD];
    __shared__ __align__(16) float sB0[NB * HD];
    __shared__ __align__(16) float sW1[NB * HD * HD];
    __shared__ __align__(16) float sB1[NB * HD];
    __shared__ __align__(16) float sW2[NB * HD * HD];
    __shared__ __align__(16) float sB2[NB * HD];
    __shared__ __align__(16) float sW3[NB * HD];
    __shared__ __align__(16) float sB3[NB];

    for (int i = threadIdx.x; i < NB * 3 * HD; i += TPB) sW0[i] = W0[i];
    for (int i = threadIdx.x; i < NB * HD; i += TPB) {
        sB0[i] = b0[i];
        sB1[i] = b1[i];
        sB2[i] = b2[i];
        sW3[i] = W3[i];   // [B,H,1] -> flat [B][H]
    }
    for (int i = threadIdx.x; i < NB * HD * HD; i += TPB) {
        sW1[i] = W1[i];
        sW2[i] = W2[i];
    }
    if (threadIdx.x < NB) sB3[threadIdx.x] = b3[threadIdx.x];
    __syncthreads();

    const uint32_t aW0 = (uint32_t)__cvta_generic_to_shared(sW0);
    const uint32_t aB0 = (uint32_t)__cvta_generic_to_shared(sB0);
    const uint32_t aW1 = (uint32_t)__cvta_generic_to_shared(sW1);
    const uint32_t aB1 = (uint32_t)__cvta_generic_to_shared(sB1);
    const uint32_t aW2 = (uint32_t)__cvta_generic_to_shared(sW2);
    const uint32_t aB2 = (uint32_t)__cvta_generic_to_shared(sB2);
    const uint32_t aW3 = (uint32_t)__cvta_generic_to_shared(sW3);

    int n = blockIdx.x * TPB + threadIdx.x;   // one point per thread
    const float* xp = x + (long)n * 3;
    u64 px0 = splat2(xp[0]);
    u64 px1 = splat2(xp[1]);
    u64 px2 = splat2(xp[2]);

    float res[NB];

    #pragma unroll 1
    for (int b = 0; b < NB; b++) {
        u64 acc[HD / 2];
        float h[HD];

        // ---- layer 0: 3 -> 32 ----
        {
            uint32_t wb = aW0 + b * 3 * HD * 4;
            uint32_t bb = aB0 + b * HD * 4;
            #pragma unroll
            for (int jp = 0; jp < HD / 2; jp++) acc[jp] = lds64(bb + jp * 8);
            #pragma unroll
            for (int d = 0; d < 3; d++) {
                u64 xd = (d == 0) ? px0 : (d == 1) ? px1 : px2;
                #pragma unroll
                for (int q = 0; q < HD / 4; q++) {
                    u64 w01, w23;
                    lds128(w01, w23, wb + d * HD * 4 + q * 16);
                    acc[2 * q]     = ffma2(xd, w01, acc[2 * q]);
                    acc[2 * q + 1] = ffma2(xd, w23, acc[2 * q + 1]);
                }
            }
            #pragma unroll
            for (int jp = 0; jp < HD / 2; jp++) {
                float a, c; unpk2(acc[jp], a, c);
                h[2 * jp]     = tanh_fast(a);
                h[2 * jp + 1] = tanh_fast(c);
            }
        }

        // ---- layers 1 & 2: 32 -> 32 ----
        #pragma unroll 1
        for (int L = 0; L < 2; L++) {
            uint32_t wb = (L == 0 ? aW1 : aW2) + b * HD * HD * 4;
            uint32_t bb = (L == 0 ? aB1 : aB2) + b * HD * 4;
            #pragma unroll
            for (int jp = 0; jp < HD / 2; jp++) acc[jp] = lds64(bb + jp * 8);
            #pragma unroll
            for (int d = 0; d < HD; d++) {
                u64 hd = splat2(h[d]);
                #pragma unroll
                for (int q = 0; q < HD / 4; q++) {
                    u64 w01, w23;
                    lds128(w01, w23, wb + d * HD * 4 + q * 16);
                    acc[2 * q]     = ffma2(hd, w01, acc[2 * q]);
                    acc[2 * q + 1] = ffma2(hd, w23, acc[2 * q + 1]);
                }
            }
            #pragma unroll
            for (int jp = 0; jp < HD / 2; jp++) {
                float a, c; unpk2(acc[jp], a, c);
                h[2 * jp]     = tanh_fast(a);
                h[2 * jp + 1] = tanh_fast(c);
            }
        }

        // ---- layer 3: 32 -> 1 (scalar reduction) ----
        {
            uint32_t wb = aW3 + b * HD * 4;
            float s = sB3[b];
            #pragma unroll
            for (int d = 0; d < HD; d++) {
                float w = ((const float*)sW3)[b * HD + d];
                (void)wb;
                s = fmaf(h[d], w, s);
            }
            res[b] = s;
        }
    }

    // out is [N, 4] row-major
    ((float4*)out)[n] = make_float4(res[0], res[1], res[2], res[3]);
}

extern "C" void kernel_launch(void* const* d_in, const int* in_sizes, int n_in,
                              void* d_out, int out_size) {
    const float* x  = (const float*)d_in[0];
    const float* W0 = (const float*)d_in[1];
    const float* b0 = (const float*)d_in[2];
    const float* W1 = (const float*)d_in[3];
    const float* b1 = (const float*)d_in[4];
    const float* W2 = (const float*)d_in[5];
    const float* b2 = (const float*)d_in[6];
    const float* W3 = (const float*)d_in[7];
    const float* b3 = (const float*)d_in[8];
    float* out = (float*)d_out;

    int grid = NPTS / TPB;   // 4096
    pfnn_kernel<<<grid, TPB>>>(x, W0, b0, W1, b1, W2, b2, W3, b3, out);
}

// round 5
// speedup vs baseline: 1.8048x; 1.4464x over previous
#include <cuda_runtime.h>
#include <cstdint>

#define NPTS 1048576
#define HD 32
#define NB 4
#define TPB 128

typedef unsigned long long u64;

// ---- packed f32x2 helpers (Blackwell) ----
__device__ __forceinline__ u64 splat2(float w) {
    u64 r; asm("mov.b64 %0, {%1, %1};" : "=l"(r) : "f"(w)); return r;
}
__device__ __forceinline__ u64 ffma2(u64 a, u64 b, u64 c) {
    u64 d; asm("fma.rn.f32x2 %0, %1, %2, %3;" : "=l"(d) : "l"(a), "l"(b), "l"(c));
    return d;
}
__device__ __forceinline__ void unpk2(u64 v, float& a, float& b) {
    asm("mov.b64 {%0, %1}, %2;" : "=f"(a), "=f"(b) : "l"(v));
}
// LDS.128 returning two 64-bit lanes == two pre-packed f32x2 weight pairs
__device__ __forceinline__ void lds128(u64& a, u64& b, uint32_t addr) {
    asm volatile("ld.shared.v2.u64 {%0, %1}, [%2];" : "=l"(a), "=l"(b) : "r"(addr));
}
__device__ __forceinline__ u64 lds64(uint32_t addr) {
    u64 a; asm volatile("ld.shared.u64 %0, [%1];" : "=l"(a) : "r"(addr));
    return a;
}
__device__ __forceinline__ float tanh_fast(float x) {
    float y; asm("tanh.approx.f32 %0, %1;" : "=f"(y) : "f"(x));
    return y;
}

__global__ __launch_bounds__(TPB, 2)
void pfnn_kernel(const float* __restrict__ x,
                 const float* __restrict__ W0, const float* __restrict__ b0,
                 const float* __restrict__ W1, const float* __restrict__ b1,
                 const float* __restrict__ W2, const float* __restrict__ b2,
                 const float* __restrict__ W3, const float* __restrict__ b3,
                 float* __restrict__ out) {
    // Weights in ORIGINAL [b][d][j] layout (j contiguous): each LDS.128 over j
    // yields two ready f32x2 weight pairs. Each loaded weight pair feeds FFMA2
    // for TWO points -> 4 FFMA2 per LDS.128 (halves L1 wavefront traffic vs R2).
    __shared__ __align__(16) float sW0[NB * 3 * HD];
    __shared__ __align__(16) float sB0[NB * HD];
    __shared__ __align__(16) float sW1[NB * HD * HD];
    __shared__ __align__(16) float sB1[NB * HD];
    __shared__ __align__(16) float sW2[NB * HD * HD];
    __shared__ __align__(16) float sB2[NB * HD];
    __shared__ __align__(16) float sW3[NB * HD];
    __shared__ __align__(16) float sB3[NB];

    for (int i = threadIdx.x; i < NB * 3 * HD; i += TPB) sW0[i] = W0[i];
    for (int i = threadIdx.x; i < NB * HD; i += TPB) {
        sB0[i] = b0[i];
        sB1[i] = b1[i];
        sB2[i] = b2[i];
        sW3[i] = W3[i];   // [B,H,1] -> flat [B][H]
    }
    for (int i = threadIdx.x; i < NB * HD * HD; i += TPB) {
        sW1[i] = W1[i];
        sW2[i] = W2[i];
    }
    if (threadIdx.x < NB) sB3[threadIdx.x] = b3[threadIdx.x];
    __syncthreads();

    const uint32_t aW0 = (uint32_t)__cvta_generic_to_shared(sW0);
    const uint32_t aB0 = (uint32_t)__cvta_generic_to_shared(sB0);
    const uint32_t aW1 = (uint32_t)__cvta_generic_to_shared(sW1);
    const uint32_t aB1 = (uint32_t)__cvta_generic_to_shared(sB1);
    const uint32_t aW2 = (uint32_t)__cvta_generic_to_shared(sW2);
    const uint32_t aB2 = (uint32_t)__cvta_generic_to_shared(sB2);

    int t = blockIdx.x * TPB + threadIdx.x;   // 2 points per thread
    const float* xp = x + (long)t * 6;
    u64 pxa0 = splat2(xp[0]), pxa1 = splat2(xp[1]), pxa2 = splat2(xp[2]);
    u64 pxb0 = splat2(xp[3]), pxb1 = splat2(xp[4]), pxb2 = splat2(xp[5]);

    float resA[NB], resB[NB];

    #pragma unroll 1
    for (int b = 0; b < NB; b++) {
        u64 accA[HD / 2], accB[HD / 2];
        float hA[HD], hB[HD];

        // ---- layer 0: 3 -> 32 ----
        {
            uint32_t wb = aW0 + b * 3 * HD * 4;
            uint32_t bb = aB0 + b * HD * 4;
            #pragma unroll
            for (int jp = 0; jp < HD / 2; jp++) {
                u64 bias = lds64(bb + jp * 8);
                accA[jp] = bias; accB[jp] = bias;
            }
            #pragma unroll
            for (int d = 0; d < 3; d++) {
                u64 xa = (d == 0) ? pxa0 : (d == 1) ? pxa1 : pxa2;
                u64 xb = (d == 0) ? pxb0 : (d == 1) ? pxb1 : pxb2;
                #pragma unroll
                for (int q = 0; q < HD / 4; q++) {
                    u64 w01, w23;
                    lds128(w01, w23, wb + d * HD * 4 + q * 16);
                    accA[2*q]   = ffma2(xa, w01, accA[2*q]);
                    accB[2*q]   = ffma2(xb, w01, accB[2*q]);
                    accA[2*q+1] = ffma2(xa, w23, accA[2*q+1]);
                    accB[2*q+1] = ffma2(xb, w23, accB[2*q+1]);
                }
            }
            #pragma unroll
            for (int jp = 0; jp < HD / 2; jp++) {
                float p, q2; unpk2(accA[jp], p, q2);
                hA[2*jp] = tanh_fast(p); hA[2*jp+1] = tanh_fast(q2);
                unpk2(accB[jp], p, q2);
                hB[2*jp] = tanh_fast(p); hB[2*jp+1] = tanh_fast(q2);
            }
        }

        // ---- layers 1 & 2: 32 -> 32 ----
        #pragma unroll 1
        for (int L = 0; L < 2; L++) {
            uint32_t wb = (L == 0 ? aW1 : aW2) + b * HD * HD * 4;
            uint32_t bb = (L == 0 ? aB1 : aB2) + b * HD * 4;
            #pragma unroll
            for (int jp = 0; jp < HD / 2; jp++) {
                u64 bias = lds64(bb + jp * 8);
                accA[jp] = bias; accB[jp] = bias;
            }
            #pragma unroll
            for (int d = 0; d < HD; d++) {
                u64 ha = splat2(hA[d]);
                u64 hb = splat2(hB[d]);
                #pragma unroll
                for (int q = 0; q < HD / 4; q++) {
                    u64 w01, w23;
                    lds128(w01, w23, wb + d * HD * 4 + q * 16);
                    accA[2*q]   = ffma2(ha, w01, accA[2*q]);
                    accB[2*q]   = ffma2(hb, w01, accB[2*q]);
                    accA[2*q+1] = ffma2(ha, w23, accA[2*q+1]);
                    accB[2*q+1] = ffma2(hb, w23, accB[2*q+1]);
                }
            }
            #pragma unroll
            for (int jp = 0; jp < HD / 2; jp++) {
                float p, q2; unpk2(accA[jp], p, q2);
                hA[2*jp] = tanh_fast(p); hA[2*jp+1] = tanh_fast(q2);
                unpk2(accB[jp], p, q2);
                hB[2*jp] = tanh_fast(p); hB[2*jp+1] = tanh_fast(q2);
            }
        }

        // ---- layer 3: 32 -> 1 (scalar reductions) ----
        {
            float sA = sB3[b], sBv = sB3[b];
            #pragma unroll
            for (int d = 0; d < HD; d++) {
                float w = sW3[b * HD + d];
                sA  = fmaf(hA[d], w, sA);
                sBv = fmaf(hB[d], w, sBv);
            }
            resA[b] = sA; resB[b] = sBv;
        }
    }

    // out is [N, 4] row-major: one float4 row per point
    float4* op = (float4*)out;
    op[2 * t]     = make_float4(resA[0], resA[1], resA[2], resA[3]);
    op[2 * t + 1] = make_float4(resB[0], resB[1], resB[2], resB[3]);
}

extern "C" void kernel_launch(void* const* d_in, const int* in_sizes, int n_in,
                              void* d_out, int out_size) {
    const float* x  = (const float*)d_in[0];
    const float* W0 = (const float*)d_in[1];
    const float* b0 = (const float*)d_in[2];
    const float* W1 = (const float*)d_in[3];
    const float* b1 = (const float*)d_in[4];
    const float* W2 = (const float*)d_in[5];
    const float* b2 = (const float*)d_in[6];
    const float* W3 = (const float*)d_in[7];
    const float* b3 = (const float*)d_in[8];
    float* out = (float*)d_out;

    int grid = (NPTS / 2) / TPB;   // 4096
    pfnn_kernel<<<grid, TPB>>>(x, W0, b0, W1, b1, W2, b2, W3, b3, out);
}

// round 7
// speedup vs baseline: 1.9167x; 1.0620x over previous
#include <cuda_runtime.h>
#include <cstdint>

#define NPTS 1048576
#define HD 32
#define NB 4
#define TPB 128

typedef unsigned long long u64;

// ---- packed f32x2 helpers (Blackwell) ----
__device__ __forceinline__ u64 splat2(float w) {
    u64 r; asm("mov.b64 %0, {%1, %1};" : "=l"(r) : "f"(w)); return r;
}
__device__ __forceinline__ u64 ffma2(u64 a, u64 b, u64 c) {
    u64 d; asm("fma.rn.f32x2 %0, %1, %2, %3;" : "=l"(d) : "l"(a), "l"(b), "l"(c));
    return d;
}
__device__ __forceinline__ void unpk2(u64 v, float& a, float& b) {
    asm("mov.b64 {%0, %1}, %2;" : "=f"(a), "=f"(b) : "l"(v));
}
// LDS.128 returning two 64-bit lanes == two pre-packed f32x2 weight pairs
__device__ __forceinline__ void lds128(u64& a, u64& b, uint32_t addr) {
    asm volatile("ld.shared.v2.u64 {%0, %1}, [%2];" : "=l"(a), "=l"(b) : "r"(addr));
}
__device__ __forceinline__ u64 lds64(uint32_t addr) {
    u64 a; asm volatile("ld.shared.u64 %0, [%1];" : "=l"(a) : "r"(addr));
    return a;
}
__device__ __forceinline__ float tanh_fast(float x) {
    float y; asm("tanh.approx.f32 %0, %1;" : "=f"(y) : "f"(x));
    return y;
}

// 3 CTAs/SM (reg cap 170): 12 warps = 3/SMSP to cover LDS(29)/MUFU(16) latency.
__global__ __launch_bounds__(TPB, 3)
void pfnn_kernel(const float* __restrict__ x,
                 const float* __restrict__ W0, const float* __restrict__ b0,
                 const float* __restrict__ W1, const float* __restrict__ b1,
                 const float* __restrict__ W2, const float* __restrict__ b2,
                 const float* __restrict__ W3, const float* __restrict__ b3,
                 float* __restrict__ out) {
    // Weights in ORIGINAL [b][d][j] layout (j contiguous): each LDS.128 over j
    // yields two ready f32x2 weight pairs, each feeding FFMA2 for TWO points
    // -> 4 FFMA2 per LDS.128.
    __shared__ __align__(16) float sW0[NB * 3 * HD];
    __shared__ __align__(16) float sB0[NB * HD];
    __shared__ __align__(16) float sW1[NB * HD * HD];
    __shared__ __align__(16) float sB1[NB * HD];
    __shared__ __align__(16) float sW2[NB * HD * HD];
    __shared__ __align__(16) float sB2[NB * HD];
    __shared__ __align__(16) float sW3[NB * HD];
    __shared__ __align__(16) float sB3[NB];

    for (int i = threadIdx.x; i < NB * 3 * HD; i += TPB) sW0[i] = W0[i];
    for (int i = threadIdx.x; i < NB * HD; i += TPB) {
        sB0[i] = b0[i];
        sB1[i] = b1[i];
        sB2[i] = b2[i];
        sW3[i] = W3[i];   // [B,H,1] -> flat [B][H]
    }
    for (int i = threadIdx.x; i < NB * HD * HD; i += TPB) {
        sW1[i] = W1[i];
        sW2[i] = W2[i];
    }
    if (threadIdx.x < NB) sB3[threadIdx.x] = b3[threadIdx.x];
    __syncthreads();

    const uint32_t aW0 = (uint32_t)__cvta_generic_to_shared(sW0);
    const uint32_t aB0 = (uint32_t)__cvta_generic_to_shared(sB0);
    const uint32_t aW1 = (uint32_t)__cvta_generic_to_shared(sW1);
    const uint32_t aB1 = (uint32_t)__cvta_generic_to_shared(sB1);
    const uint32_t aW2 = (uint32_t)__cvta_generic_to_shared(sW2);
    const uint32_t aB2 = (uint32_t)__cvta_generic_to_shared(sB2);

    int t = blockIdx.x * TPB + threadIdx.x;   // 2 points per thread
    const float* xp = x + (long)t * 6;
    u64 pxa0 = splat2(xp[0]), pxa1 = splat2(xp[1]), pxa2 = splat2(xp[2]);
    u64 pxb0 = splat2(xp[3]), pxb1 = splat2(xp[4]), pxb2 = splat2(xp[5]);

    float resA[NB], resB[NB];

    #pragma unroll 1
    for (int b = 0; b < NB; b++) {
        u64 accA[HD / 2], accB[HD / 2];
        float hA[HD], hB[HD];

        // ---- layer 0: 3 -> 32 ----
        {
            uint32_t wb = aW0 + b * 3 * HD * 4;
            uint32_t bb = aB0 + b * HD * 4;
            #pragma unroll
            for (int jp = 0; jp < HD / 2; jp++) {
                u64 bias = lds64(bb + jp * 8);
                accA[jp] = bias; accB[jp] = bias;
            }
            #pragma unroll
            for (int d = 0; d < 3; d++) {
                u64 xa = (d == 0) ? pxa0 : (d == 1) ? pxa1 : pxa2;
                u64 xb = (d == 0) ? pxb0 : (d == 1) ? pxb1 : pxb2;
                #pragma unroll
                for (int q = 0; q < HD / 4; q++) {
                    u64 w01, w23;
                    lds128(w01, w23, wb + d * HD * 4 + q * 16);
                    accA[2*q]   = ffma2(xa, w01, accA[2*q]);
                    accB[2*q]   = ffma2(xb, w01, accB[2*q]);
                    accA[2*q+1] = ffma2(xa, w23, accA[2*q+1]);
                    accB[2*q+1] = ffma2(xb, w23, accB[2*q+1]);
                }
            }
            #pragma unroll
            for (int jp = 0; jp < HD / 2; jp++) {
                float p, q2; unpk2(accA[jp], p, q2);
                hA[2*jp] = tanh_fast(p); hA[2*jp+1] = tanh_fast(q2);
                unpk2(accB[jp], p, q2);
                hB[2*jp] = tanh_fast(p); hB[2*jp+1] = tanh_fast(q2);
            }
        }

        // ---- layers 1 & 2: 32 -> 32 ----
        #pragma unroll 1
        for (int L = 0; L < 2; L++) {
            uint32_t wb = (L == 0 ? aW1 : aW2) + b * HD * HD * 4;
            uint32_t bb = (L == 0 ? aB1 : aB2) + b * HD * 4;
            #pragma unroll
            for (int jp = 0; jp < HD / 2; jp++) {
                u64 bias = lds64(bb + jp * 8);
                accA[jp] = bias; accB[jp] = bias;
            }
            #pragma unroll
            for (int d = 0; d < HD; d++) {
                u64 ha = splat2(hA[d]);
                u64 hb = splat2(hB[d]);
                #pragma unroll
                for (int q = 0; q < HD / 4; q++) {
                    u64 w01, w23;
                    lds128(w01, w23, wb + d * HD * 4 + q * 16);
                    accA[2*q]   = ffma2(ha, w01, accA[2*q]);
                    accB[2*q]   = ffma2(hb, w01, accB[2*q]);
                    accA[2*q+1] = ffma2(ha, w23, accA[2*q+1]);
                    accB[2*q+1] = ffma2(hb, w23, accB[2*q+1]);
                }
            }
            #pragma unroll
            for (int jp = 0; jp < HD / 2; jp++) {
                float p, q2; unpk2(accA[jp], p, q2);
                hA[2*jp] = tanh_fast(p); hA[2*jp+1] = tanh_fast(q2);
                unpk2(accB[jp], p, q2);
                hB[2*jp] = tanh_fast(p); hB[2*jp+1] = tanh_fast(q2);
            }
        }

        // ---- layer 3: 32 -> 1 (scalar reductions) ----
        {
            float sA = sB3[b], sBv = sB3[b];
            #pragma unroll
            for (int d = 0; d < HD; d++) {
                float w = sW3[b * HD + d];
                sA  = fmaf(hA[d], w, sA);
                sBv = fmaf(hB[d], w, sBv);
            }
            resA[b] = sA; resB[b] = sBv;
        }
    }

    // out is [N, 4] row-major: one float4 row per point
    float4* op = (float4*)out;
    op[2 * t]     = make_float4(resA[0], resA[1], resA[2], resA[3]);
    op[2 * t + 1] = make_float4(resB[0], resB[1], resB[2], resB[3]);
}

extern "C" void kernel_launch(void* const* d_in, const int* in_sizes, int n_in,
                              void* d_out, int out_size) {
    const float* x  = (const float*)d_in[0];
    const float* W0 = (const float*)d_in[1];
    const float* b0 = (const float*)d_in[2];
    const float* W1 = (const float*)d_in[3];
    const float* b1 = (const float*)d_in[4];
    const float* W2 = (const float*)d_in[5];
    const float* b2 = (const float*)d_in[6];
    const float* W3 = (const float*)d_in[7];
    const float* b3 = (const float*)d_in[8];
    float* out = (float*)d_out;

    int grid = (NPTS / 2) / TPB;   // 4096
    pfnn_kernel<<<grid, TPB>>>(x, W0, b0, W1, b1, W2, b2, W3, b3, out);
}